// round 16
// baseline (speedup 1.0000x reference)
#include <cuda_runtime.h>
#include <cuda_pipeline.h>
#include <cstdint>

#define NN 1000
#define D 128
#define STR 384      // K_att/V_att innermost stride in floats (3 * 128)
#define NW 8         // warps per CTA
#define CH 3         // adjacent nodes per chunk, layers 0/1 (K+V)
#define CH2 6        // adjacent nodes per chunk, layer 2 (K only)

__device__ __forceinline__ float4 zero4() { return make_float4(0.f, 0.f, 0.f, 0.f); }

// One CTA per batch, 8 warps, occupancy 4 (single wave of 512 CTAs).
// R15 winner (CH=3 cp.async double buffer, cross-layer prologue overlap,
// smem logit staging) + early output zeroing: the 4KB row of zeros is issued
// before layer 0 and drains under the main memory traffic, so the epilogue is
// a bare ~cnt-element scatter. __syncthreads between zero and scatter gives
// the required write ordering.

__global__ __launch_bounds__(256, 4)
void decoder_fused_kernel(
    const float* __restrict__ query,
    const float* __restrict__ K_att,
    const float* __restrict__ V_att,
    const int* __restrict__ mask,          // bool serialized as int32
    const float* __restrict__ W0_w,
    const float* __restrict__ W0_b,
    const float* __restrict__ Wq_w,
    const float* __restrict__ Wq_b,
    float* __restrict__ out)
{
    __shared__ __align__(16) float ring[NW * 2 * CH * 256];  // 48 KB
    __shared__ unsigned short nlist[NN];                      // 2 KB
    __shared__ float ss[NN];                                  // 4 KB staged logits
    __shared__ int wcnt[NW + 1];
    __shared__ __align__(16) float qs[D];
    __shared__ __align__(16) float mo[D];
    __shared__ float M2s, L2s;

    // merge scratch aliased on warp 0's ring area (ring[0..1536))
    float*  m_s = ring;                   // [NW][32]
    float*  l_s = ring + 256;             // [NW][32]
    float4* a_s = (float4*)(ring + 512);  // [NW][32]

    const int b = blockIdx.x;
    const int tid = threadIdx.x;
    const int wid = tid >> 5;
    const int lane = tid & 31;
    const int loff = 4 * lane;
    const float NEG = __int_as_float(0xff800000);  // -inf

    if (tid < D) qs[tid] = query[(size_t)b * D + tid];

    float* orow = out + (size_t)b * NN;

    // ---- Parallel compaction: warp w scans nodes [125w, 125(w+1)) ----
    const int* mrow = mask + (size_t)b * NN;
    {
        const int s0 = wid * 125;
        int cnt_w = 0;
        for (int start = s0; start < s0 + 125; start += 32) {
            int n = start + lane;
            bool keep = (n < s0 + 125) && (mrow[n] == 0);
            cnt_w += __popc(__ballot_sync(0xffffffffu, keep));
        }
        if (lane == 0) wcnt[wid] = cnt_w;
        __syncthreads();
        if (tid == 0) {
            int acc = 0;
            #pragma unroll
            for (int w = 0; w < NW; ++w) { int t = wcnt[w]; wcnt[w] = acc; acc += t; }
            wcnt[NW] = acc;
        }
        __syncthreads();
        int base = wcnt[wid];
        for (int start = s0; start < s0 + 125; start += 32) {
            int n = start + lane;
            bool keep = (n < s0 + 125) && (mrow[n] == 0);
            unsigned bal = __ballot_sync(0xffffffffu, keep);
            if (keep) nlist[base + __popc(bal & ((1u << lane) - 1u))] = (unsigned short)n;
            base += __popc(bal);
        }
    }
    // EARLY ZERO: fire-and-forget stores, drain under layer-0 traffic.
    // Ordered before the epilogue scatter by the intervening __syncthreads.
    for (int n = tid; n < NN; n += 256) orow[n] = 0.0f;
    __syncthreads();
    const int cnt  = wcnt[NW];
    const int nch  = (cnt + CH - 1) / CH;
    const int nch2 = (cnt + CH2 - 1) / CH2;

    const float* Kb = K_att + (size_t)b * NN * STR;
    const float* Vb = V_att + (size_t)b * NN * STR;
    float* rw = ring + wid * (2 * CH * 256);

    // stage CH nodes (K+V) of layer l, chunk c, into buf; always 1 commit
    auto stageKV = [&](int l, int c, float* buf) {
        if (c < nch) {
            const int cbase = l * D + loff;
            #pragma unroll
            for (int j = 0; j < CH; ++j) {
                int i = c * CH + j;
                int node = nlist[i < cnt ? i : 0];
                size_t o = (size_t)node * STR + cbase;
                __pipeline_memcpy_async(buf + j * 256 + loff, Kb + o, 16);
                __pipeline_memcpy_async(buf + j * 256 + 128 + loff, Vb + o, 16);
            }
        }
        __pipeline_commit();
    };
    // stage CH2 nodes (K only, layer 2) of chunk c into buf; always 1 commit
    auto stageK2 = [&](int c, float* buf) {
        if (c < nch2) {
            const int cbase = 2 * D + loff;
            #pragma unroll
            for (int j = 0; j < CH2; ++j) {
                int i = c * CH2 + j;
                int node = nlist[i < cnt ? i : 0];
                __pipeline_memcpy_async(buf + j * 128 + loff,
                                        Kb + (size_t)node * STR + cbase, 16);
            }
        }
        __pipeline_commit();
    };
    // consume CH nodes of a K+V buffer into flash state
    auto consumeKV = [&](const float* buf, int c, const float4 q4,
                         float& m, float& lsum, float4& acc) {
        #pragma unroll
        for (int j = 0; j < CH; ++j) {
            const float4 k4 = *(const float4*)(buf + j * 256 + loff);
            const float4 v4 = *(const float4*)(buf + j * 256 + 128 + loff);
            float s = k4.x * q4.x + k4.y * q4.y + k4.z * q4.z + k4.w * q4.w;
            s += __shfl_xor_sync(0xffffffffu, s, 1);
            s += __shfl_xor_sync(0xffffffffu, s, 2);
            s = (c * CH + j < cnt) ? s * 0.25f : NEG;   // 1/sqrt(16)
            const float mn = fmaxf(m, s);
            const float cc = __expf(m - mn);
            const float e = __expf(s - mn);
            lsum = lsum * cc + e;
            acc.x = acc.x * cc + e * v4.x;
            acc.y = acc.y * cc + e * v4.y;
            acc.z = acc.z * cc + e * v4.z;
            acc.w = acc.w * cc + e * v4.w;
            m = mn;
        }
    };
    // 8-warp flash merge of partials in scratch -> normalized result in mo
    auto mergeFlash = [&]() {
        const int ln = tid;  // tid < 32
        float M = m_s[ln];
        #pragma unroll
        for (int w = 1; w < NW; ++w) M = fmaxf(M, m_s[w * 32 + ln]);
        float L = 0.f, ax = 0.f, ay = 0.f, az = 0.f, aw = 0.f;
        #pragma unroll
        for (int w = 0; w < NW; ++w) {
            const float cc = __expf(m_s[w * 32 + ln] - M);
            L += l_s[w * 32 + ln] * cc;
            const float4 a = a_s[w * 32 + ln];
            ax += a.x * cc; ay += a.y * cc; az += a.z * cc; aw += a.w * cc;
        }
        const float inv = 1.0f / L;
        mo[4 * ln + 0] = ax * inv;
        mo[4 * ln + 1] = ay * inv;
        mo[4 * ln + 2] = az * inv;
        mo[4 * ln + 3] = aw * inv;
    };

    // ==================== Layer 0 ====================
    stageKV(0, wid, rw);
    stageKV(0, wid + NW, rw + CH * 256);
    {
        const float4 q4 = *(const float4*)(qs + loff);
        float m = -1e30f, lsum = 0.0f;
        float4 acc = zero4();
        int it = 0;
        for (int c = wid; c < nch; c += NW, ++it) {
            __pipeline_wait_prior(1);
            float* buf = rw + (it & 1) * (CH * 256);
            consumeKV(buf, c, q4, m, lsum, acc);
            stageKV(0, c + 2 * NW, buf);
        }
        __pipeline_wait_prior(0);
        __syncthreads();   // warp0 ring area dead -> scratch
        m_s[wid * 32 + lane] = m;
        l_s[wid * 32 + lane] = lsum;
        a_s[wid * 32 + lane] = acc;
    }
    __syncthreads();
    // OVERLAP: warps 1..7 stage layer-1 prologue during merge + matmul
    if (wid >= 1) {
        stageKV(1, wid, rw);
        stageKV(1, wid + NW, rw + CH * 256);
    }
    if (tid < 32) mergeFlash();
    __syncthreads();
    if (tid < D) {   // qs = mo @ W0.T + b0
        const float* Wr = W0_w + tid * D;
        float a2 = W0_b[tid];
        #pragma unroll 8
        for (int d = 0; d < D; ++d) a2 = fmaf(mo[d], Wr[d], a2);
        qs[tid] = a2;
    }
    __syncthreads();
    if (wid == 0) {  // scratch dead now
        stageKV(1, 0, rw);
        stageKV(1, NW, rw + CH * 256);
    }

    // ==================== Layer 1 ====================
    {
        const float4 q4 = *(const float4*)(qs + loff);
        float m = -1e30f, lsum = 0.0f;
        float4 acc = zero4();
        int it = 0;
        for (int c = wid; c < nch; c += NW, ++it) {
            __pipeline_wait_prior(1);
            float* buf = rw + (it & 1) * (CH * 256);
            consumeKV(buf, c, q4, m, lsum, acc);
            stageKV(1, c + 2 * NW, buf);
        }
        __pipeline_wait_prior(0);
        __syncthreads();
        m_s[wid * 32 + lane] = m;
        l_s[wid * 32 + lane] = lsum;
        a_s[wid * 32 + lane] = acc;
    }
    __syncthreads();
    // OVERLAP: warps 1..7 stage layer-2 prologue during merge + 2 matmuls
    if (wid >= 1) {
        stageK2(wid, rw);
        stageK2(wid + NW, rw + CH2 * 128);
    }
    if (tid < 32) mergeFlash();
    __syncthreads();
    if (tid < D) {   // qs = mo @ W0.T + b0
        const float* Wr = W0_w + tid * D;
        float a2 = W0_b[tid];
        #pragma unroll 8
        for (int d = 0; d < D; ++d) a2 = fmaf(mo[d], Wr[d], a2);
        qs[tid] = a2;
    }
    __syncthreads();
    if (tid < D) {   // mo = qs @ Wq.T + bq   (q_final)
        const float* Wr = Wq_w + tid * D;
        float a2 = Wq_b[tid];
        #pragma unroll 8
        for (int d = 0; d < D; ++d) a2 = fmaf(qs[d], Wr[d], a2);
        mo[tid] = a2;
    }
    __syncthreads();
    if (wid == 0) {
        stageK2(0, rw);
        stageK2(NW, rw + CH2 * 128);
    }

    // ==================== Layer 2: 1-head, clip=10 ====================
    {
        const float4 q4 = *(const float4*)(mo + loff);
        float m = -1e30f, lsum = 0.0f;
        int it = 0;
        for (int c = wid; c < nch2; c += NW, ++it) {
            __pipeline_wait_prior(1);
            float* buf = rw + (it & 1) * (CH2 * 128);
            #pragma unroll
            for (int j = 0; j < CH2; ++j) {
                const int i = c * CH2 + j;
                const float4 k4 = *(const float4*)(buf + j * 128 + loff);
                float s = k4.x * q4.x + k4.y * q4.y + k4.z * q4.z + k4.w * q4.w;
                #pragma unroll
                for (int d = 1; d < 32; d <<= 1)
                    s += __shfl_xor_sync(0xffffffffu, s, d);
                s *= 0.08838834764831845f;   // 1/sqrt(128)
                s = 10.0f * (1.0f - __fdividef(2.0f, __expf(2.0f * s) + 1.0f));  // 10*tanh
                if (i < cnt) {
                    if (lane == 0) ss[i] = s;
                } else s = NEG;
                const float mn = fmaxf(m, s);
                lsum = lsum * __expf(m - mn) + __expf(s - mn);
                m = mn;
            }
            stageK2(c + 2 * NW, buf);
        }
        __pipeline_wait_prior(0);
        __syncthreads();
        if (lane == 0) { m_s[wid * 32] = m; l_s[wid * 32] = lsum; }
    }
    __syncthreads();
    if (tid == 0) {
        float M = m_s[0];
        #pragma unroll
        for (int w = 1; w < NW; ++w) M = fmaxf(M, m_s[w * 32]);
        float L = 0.f;
        #pragma unroll
        for (int w = 0; w < NW; ++w) L += l_s[w * 32] * __expf(m_s[w * 32] - M);
        M2s = M;
        L2s = 1.0f / L;
    }
    __syncthreads();

    // epilogue: bare scatter of normalized weights (row already zeroed early)
    {
        const float M = M2s, Li = L2s;
        for (int i = tid; i < cnt; i += 256)
            orow[nlist[i]] = __expf(ss[i] - M) * Li;
    }
}

extern "C" void kernel_launch(void* const* d_in, const int* in_sizes, int n_in,
                              void* d_out, int out_size) {
    const float* query = (const float*)d_in[0];
    const float* K_att = (const float*)d_in[1];
    const float* V_att = (const float*)d_in[2];
    const int*   mask  = (const int*)d_in[3];
    const float* W0_w  = (const float*)d_in[4];
    const float* W0_b  = (const float*)d_in[5];
    const float* Wq_w  = (const float*)d_in[6];
    const float* Wq_b  = (const float*)d_in[7];
    float* out = (float*)d_out;

    decoder_fused_kernel<<<512, 256>>>(query, K_att, V_att, mask,
                                       W0_w, W0_b, Wq_w, Wq_b, out);
}

// round 17
// speedup vs baseline: 1.0105x; 1.0105x over previous
#include <cuda_runtime.h>
#include <cuda_pipeline.h>
#include <cstdint>

#define NN 1000
#define D 128
#define STR 384      // K_att/V_att innermost stride in floats (3 * 128)
#define NW 12        // warps per CTA (41.5 warps/SM resident)
#define THREADS 384
#define CH 2         // adjacent nodes per chunk, layers 0/1 (K+V)
#define CH2 4        // adjacent nodes per chunk, layer 2 (K only)

__device__ __forceinline__ float4 zero4() { return make_float4(0.f, 0.f, 0.f, 0.f); }

// One CTA per batch, 12 warps, occupancy 4 (single wave of 512 CTAs).
// R15/R16 skeleton (cp.async double buffer, adjacent-node chunks, cross-layer
// prologue overlap, smem logit staging, early output zeroing) with 1.5x the
// resident warps (R5's +3% BW lever). Ring stays 48 KB: 12 warps x 2 bufs x
// 2 nodes x 1KB. Merge scratch aliases warps 0-2's ring area, so prologue
// overlap staging is done by warps >=3; warps 0-2 stage after the matmul.

__global__ __launch_bounds__(THREADS, 4)
void decoder_fused_kernel(
    const float* __restrict__ query,
    const float* __restrict__ K_att,
    const float* __restrict__ V_att,
    const int* __restrict__ mask,          // bool serialized as int32
    const float* __restrict__ W0_w,
    const float* __restrict__ W0_b,
    const float* __restrict__ Wq_w,
    const float* __restrict__ Wq_b,
    float* __restrict__ out)
{
    __shared__ __align__(16) float ring[NW * 2 * CH * 256];  // 48 KB
    __shared__ unsigned short nlist[NN];                      // 2 KB
    __shared__ float ss[NN];                                  // 4 KB staged logits
    __shared__ int wcnt[NW + 1];
    __shared__ __align__(16) float qs[D];
    __shared__ __align__(16) float mo[D];
    __shared__ float M2s, L2s;

    // merge scratch aliased on ring[0 .. 2304) (covers warps 0-2's area)
    float*  m_s = ring;                   // [NW][32]
    float*  l_s = ring + NW * 32;         // [NW][32]
    float4* a_s = (float4*)(ring + 2 * NW * 32);  // [NW][32]

    const int b = blockIdx.x;
    const int tid = threadIdx.x;
    const int wid = tid >> 5;
    const int lane = tid & 31;
    const int loff = 4 * lane;
    const float NEG = __int_as_float(0xff800000);  // -inf

    if (tid < D) qs[tid] = query[(size_t)b * D + tid];

    float* orow = out + (size_t)b * NN;

    // ---- Parallel compaction: warp w scans its contiguous node range ----
    const int* mrow = mask + (size_t)b * NN;
    {
        const int s0 = (wid * NN) / NW;
        const int s1 = ((wid + 1) * NN) / NW;
        int cnt_w = 0;
        for (int start = s0; start < s1; start += 32) {
            int n = start + lane;
            bool keep = (n < s1) && (mrow[n] == 0);
            cnt_w += __popc(__ballot_sync(0xffffffffu, keep));
        }
        if (lane == 0) wcnt[wid] = cnt_w;
        __syncthreads();
        if (tid == 0) {
            int acc = 0;
            #pragma unroll
            for (int w = 0; w < NW; ++w) { int t = wcnt[w]; wcnt[w] = acc; acc += t; }
            wcnt[NW] = acc;
        }
        __syncthreads();
        int base = wcnt[wid];
        for (int start = s0; start < s1; start += 32) {
            int n = start + lane;
            bool keep = (n < s1) && (mrow[n] == 0);
            unsigned bal = __ballot_sync(0xffffffffu, keep);
            if (keep) nlist[base + __popc(bal & ((1u << lane) - 1u))] = (unsigned short)n;
            base += __popc(bal);
        }
    }
    // EARLY ZERO: fire-and-forget stores, drain under layer-0 traffic.
    for (int n = tid; n < NN; n += THREADS) orow[n] = 0.0f;
    __syncthreads();
    const int cnt  = wcnt[NW];
    const int nch  = (cnt + CH - 1) / CH;
    const int nch2 = (cnt + CH2 - 1) / CH2;

    const float* Kb = K_att + (size_t)b * NN * STR;
    const float* Vb = V_att + (size_t)b * NN * STR;
    float* rw = ring + wid * (2 * CH * 256);

    // stage CH nodes (K+V) of layer l, chunk c, into buf; always 1 commit
    auto stageKV = [&](int l, int c, float* buf) {
        if (c < nch) {
            const int cbase = l * D + loff;
            #pragma unroll
            for (int j = 0; j < CH; ++j) {
                int i = c * CH + j;
                int node = nlist[i < cnt ? i : 0];
                size_t o = (size_t)node * STR + cbase;
                __pipeline_memcpy_async(buf + j * 256 + loff, Kb + o, 16);
                __pipeline_memcpy_async(buf + j * 256 + 128 + loff, Vb + o, 16);
            }
        }
        __pipeline_commit();
    };
    // stage CH2 nodes (K only, layer 2) of chunk c into buf; always 1 commit
    auto stageK2 = [&](int c, float* buf) {
        if (c < nch2) {
            const int cbase = 2 * D + loff;
            #pragma unroll
            for (int j = 0; j < CH2; ++j) {
                int i = c * CH2 + j;
                int node = nlist[i < cnt ? i : 0];
                __pipeline_memcpy_async(buf + j * 128 + loff,
                                        Kb + (size_t)node * STR + cbase, 16);
            }
        }
        __pipeline_commit();
    };
    // consume CH nodes of a K+V buffer into flash state
    auto consumeKV = [&](const float* buf, int c, const float4 q4,
                         float& m, float& lsum, float4& acc) {
        #pragma unroll
        for (int j = 0; j < CH; ++j) {
            const float4 k4 = *(const float4*)(buf + j * 256 + loff);
            const float4 v4 = *(const float4*)(buf + j * 256 + 128 + loff);
            float s = k4.x * q4.x + k4.y * q4.y + k4.z * q4.z + k4.w * q4.w;
            s += __shfl_xor_sync(0xffffffffu, s, 1);
            s += __shfl_xor_sync(0xffffffffu, s, 2);
            s = (c * CH + j < cnt) ? s * 0.25f : NEG;   // 1/sqrt(16)
            const float mn = fmaxf(m, s);
            const float cc = __expf(m - mn);
            const float e = __expf(s - mn);
            lsum = lsum * cc + e;
            acc.x = acc.x * cc + e * v4.x;
            acc.y = acc.y * cc + e * v4.y;
            acc.z = acc.z * cc + e * v4.z;
            acc.w = acc.w * cc + e * v4.w;
            m = mn;
        }
    };
    // 12-warp flash merge of partials in scratch -> normalized result in mo
    auto mergeFlash = [&]() {
        const int ln = tid;  // tid < 32
        float M = m_s[ln];
        #pragma unroll
        for (int w = 1; w < NW; ++w) M = fmaxf(M, m_s[w * 32 + ln]);
        float L = 0.f, ax = 0.f, ay = 0.f, az = 0.f, aw = 0.f;
        #pragma unroll
        for (int w = 0; w < NW; ++w) {
            const float cc = __expf(m_s[w * 32 + ln] - M);
            L += l_s[w * 32 + ln] * cc;
            const float4 a = a_s[w * 32 + ln];
            ax += a.x * cc; ay += a.y * cc; az += a.z * cc; aw += a.w * cc;
        }
        const float inv = 1.0f / L;
        mo[4 * ln + 0] = ax * inv;
        mo[4 * ln + 1] = ay * inv;
        mo[4 * ln + 2] = az * inv;
        mo[4 * ln + 3] = aw * inv;
    };

    // ==================== Layer 0 ====================
    stageKV(0, wid, rw);
    stageKV(0, wid + NW, rw + CH * 256);
    {
        const float4 q4 = *(const float4*)(qs + loff);
        float m = -1e30f, lsum = 0.0f;
        float4 acc = zero4();
        int it = 0;
        for (int c = wid; c < nch; c += NW, ++it) {
            __pipeline_wait_prior(1);
            float* buf = rw + (it & 1) * (CH * 256);
            consumeKV(buf, c, q4, m, lsum, acc);
            stageKV(0, c + 2 * NW, buf);
        }
        __pipeline_wait_prior(0);
        __syncthreads();   // scratch area (warps 0-2 rings) dead
        m_s[wid * 32 + lane] = m;
        l_s[wid * 32 + lane] = lsum;
        a_s[wid * 32 + lane] = acc;
    }
    __syncthreads();
    // OVERLAP: warps 3..11 stage layer-1 prologue during merge + matmul
    if (wid >= 3) {
        stageKV(1, wid, rw);
        stageKV(1, wid + NW, rw + CH * 256);
    }
    if (tid < 32) mergeFlash();
    __syncthreads();
    if (tid < D) {   // qs = mo @ W0.T + b0
        const float* Wr = W0_w + tid * D;
        float a2 = W0_b[tid];
        #pragma unroll 8
        for (int d = 0; d < D; ++d) a2 = fmaf(mo[d], Wr[d], a2);
        qs[tid] = a2;
    }
    __syncthreads();
    if (wid < 3) {   // scratch dead now
        stageKV(1, wid, rw);
        stageKV(1, wid + NW, rw + CH * 256);
    }

    // ==================== Layer 1 ====================
    {
        const float4 q4 = *(const float4*)(qs + loff);
        float m = -1e30f, lsum = 0.0f;
        float4 acc = zero4();
        int it = 0;
        for (int c = wid; c < nch; c += NW, ++it) {
            __pipeline_wait_prior(1);
            float* buf = rw + (it & 1) * (CH * 256);
            consumeKV(buf, c, q4, m, lsum, acc);
            stageKV(1, c + 2 * NW, buf);
        }
        __pipeline_wait_prior(0);
        __syncthreads();
        m_s[wid * 32 + lane] = m;
        l_s[wid * 32 + lane] = lsum;
        a_s[wid * 32 + lane] = acc;
    }
    __syncthreads();
    // OVERLAP: warps 3..11 stage layer-2 prologue during merge + 2 matmuls
    if (wid >= 3) {
        stageK2(wid, rw);
        stageK2(wid + NW, rw + CH2 * 128);
    }
    if (tid < 32) mergeFlash();
    __syncthreads();
    if (tid < D) {   // qs = mo @ W0.T + b0
        const float* Wr = W0_w + tid * D;
        float a2 = W0_b[tid];
        #pragma unroll 8
        for (int d = 0; d < D; ++d) a2 = fmaf(mo[d], Wr[d], a2);
        qs[tid] = a2;
    }
    __syncthreads();
    if (tid < D) {   // mo = qs @ Wq.T + bq   (q_final)
        const float* Wr = Wq_w + tid * D;
        float a2 = Wq_b[tid];
        #pragma unroll 8
        for (int d = 0; d < D; ++d) a2 = fmaf(qs[d], Wr[d], a2);
        mo[tid] = a2;
    }
    __syncthreads();
    if (wid < 3) {
        stageK2(wid, rw);
        stageK2(wid + NW, rw + CH2 * 128);
    }

    // ==================== Layer 2: 1-head, clip=10 ====================
    {
        const float4 q4 = *(const float4*)(mo + loff);
        float m = -1e30f, lsum = 0.0f;
        int it = 0;
        for (int c = wid; c < nch2; c += NW, ++it) {
            __pipeline_wait_prior(1);
            float* buf = rw + (it & 1) * (CH2 * 128);
            #pragma unroll
            for (int j = 0; j < CH2; ++j) {
                const int i = c * CH2 + j;
                const float4 k4 = *(const float4*)(buf + j * 128 + loff);
                float s = k4.x * q4.x + k4.y * q4.y + k4.z * q4.z + k4.w * q4.w;
                #pragma unroll
                for (int d = 1; d < 32; d <<= 1)
                    s += __shfl_xor_sync(0xffffffffu, s, d);
                s *= 0.08838834764831845f;   // 1/sqrt(128)
                s = 10.0f * (1.0f - __fdividef(2.0f, __expf(2.0f * s) + 1.0f));  // 10*tanh
                if (i < cnt) {
                    if (lane == 0) ss[i] = s;
                } else s = NEG;
                const float mn = fmaxf(m, s);
                lsum = lsum * __expf(m - mn) + __expf(s - mn);
                m = mn;
            }
            stageK2(c + 2 * NW, buf);
        }
        __pipeline_wait_prior(0);
        __syncthreads();
        if (lane == 0) { m_s[wid * 32] = m; l_s[wid * 32] = lsum; }
    }
    __syncthreads();
    if (tid == 0) {
        float M = m_s[0];
        #pragma unroll
        for (int w = 1; w < NW; ++w) M = fmaxf(M, m_s[w * 32]);
        float L = 0.f;
        #pragma unroll
        for (int w = 0; w < NW; ++w) L += l_s[w * 32] * __expf(m_s[w * 32] - M);
        M2s = M;
        L2s = 1.0f / L;
    }
    __syncthreads();

    // epilogue: bare scatter of normalized weights (row already zeroed early)
    {
        const float M = M2s, Li = L2s;
        for (int i = tid; i < cnt; i += THREADS)
            orow[nlist[i]] = __expf(ss[i] - M) * Li;
    }
}

extern "C" void kernel_launch(void* const* d_in, const int* in_sizes, int n_in,
                              void* d_out, int out_size) {
    const float* query = (const float*)d_in[0];
    const float* K_att = (const float*)d_in[1];
    const float* V_att = (const float*)d_in[2];
    const int*   mask  = (const int*)d_in[3];
    const float* W0_w  = (const float*)d_in[4];
    const float* W0_b  = (const float*)d_in[5];
    const float* Wq_w  = (const float*)d_in[6];
    const float* Wq_b  = (const float*)d_in[7];
    float* out = (float*)d_out;

    decoder_fused_kernel<<<512, THREADS>>>(query, K_att, V_att, mask,
                                           W0_w, W0_b, Wq_w, Wq_b, out);
}